// round 10
// baseline (speedup 1.0000x reference)
#include <cuda_runtime.h>

#define DIM 256
#define NCOL 16
#define BATCH 65536
typedef unsigned long long ull;

__device__ float g_Cpart[8][81 * 8];   // per-j-chunk partial C tensors
__device__ float g_C[81 * 8];          // summed C (filled by last setup block)
__device__ unsigned g_ticket;          // block-completion ticket (self-resetting)

__device__ __forceinline__ float2 cmul(float2 a, float2 b) {
    return make_float2(a.x * b.x - a.y * b.y, a.x * b.y + a.y * b.x);
}
__device__ __forceinline__ void ffma2(ull& d, ull a, ull b) {
    asm("fma.rn.f32x2 %0, %1, %2, %0;" : "+l"(d) : "l"(a), "l"(b));
}
__device__ __forceinline__ ull mul2(ull a, ull b) {
    ull r;
    asm("mul.rn.f32x2 %0, %1, %2;" : "=l"(r) : "l"(a), "l"(b));
    return r;
}
__device__ __forceinline__ ull add2(ull a, ull b) {
    ull r;
    asm("add.rn.f32x2 %0, %1, %2;" : "=l"(r) : "l"(a), "l"(b));
    return r;
}
__device__ __forceinline__ ull dup2(float p) {
    ull r;
    asm("mov.b64 %0, {%1, %2};" : "=l"(r) : "f"(p), "f"(p));
    return r;
}
__device__ __forceinline__ float2 shfl2(float2 v, int src) {
    float2 r;
    r.x = __shfl_sync(0xffffffffu, v.x, src);
    r.y = __shfl_sync(0xffffffffu, v.y, src);
    return r;
}

// swizzled smem index for M: row j (128 B), column XOR'd by j&15 -> conflict-free
#define SIDX(j, c) (((j) << 4) | ((c) ^ ((j) & 15)))

// ---------------------------------------------------------------------------
// K1 (fused setup): 64 blocks = (8 wires i) x (8 j-chunks q), 256 threads.
// Phase A: all-register sim of the 16 relevant columns (8 warps x 2 cols).
// Phase B: swizzled smem M; BC slice for (i, q) -> g_Cpart.
// Phase C: LAST block sums the 8 partials into g_C (threadfence+ticket).
// ---------------------------------------------------------------------------
__global__ void __launch_bounds__(256) fused_setup(const float* __restrict__ params) {
    __shared__ float2 Ms[DIM * NCOL];    // 32 KB, swizzled
    __shared__ float2 G[16][4];
    __shared__ float Csh[81];
    __shared__ unsigned s_ticket;

    int t = threadIdx.x;
    int ln = t & 31;
    int w = t >> 5;                      // warp id = column pair
    int i = blockIdx.x & 7;              // output wire
    int q = blockIdx.x >> 3;             // j chunk

    if (t < 16) {
        int layer = t >> 3, wi = t & 7;
        const float* p = params + layer * 24 + wi * 3;
        float cx, sx, cy, sy, cz, sz;
        __sincosf(0.5f * p[0], &sx, &cx);
        __sincosf(0.5f * p[1], &sy, &cy);
        __sincosf(0.5f * p[2], &sz, &cz);
        float2 a00 = make_float2( cy * cx,  sy * sx);
        float2 a01 = make_float2(-sy * cx, -cy * sx);
        float2 a10 = make_float2( sy * cx, -cy * sx);
        float2 a11 = make_float2( cy * cx, -sy * sx);
        float2 e0 = make_float2(cz, -sz), e1 = make_float2(cz, sz);
        G[t][0] = cmul(e0, a00);
        G[t][1] = cmul(e0, a01);
        G[t][2] = cmul(e1, a10);
        G[t][3] = cmul(e1, a11);
    }
    if (t < 81) Csh[t] = 0.f;
    __syncthreads();

    // -------- Phase A: register sim (warp w owns columns 2w, 2w+1) --------
    float2 st[2][8];
#pragma unroll
    for (int h = 0; h < 2; ++h)
#pragma unroll
        for (int r = 0; r < 8; ++r)
            st[h][r] = make_float2((r == w && ln == (h << 4)) ? 1.f : 0.f, 0.f);

#pragma unroll
    for (int layer = 0; layer < 2; ++layer) {
#pragma unroll
        for (int wi = 0; wi < 8; ++wi) {
            int g = layer * 8 + wi;
            float2 g00 = G[g][0], g01 = G[g][1], g10 = G[g][2], g11 = G[g][3];
            if (wi < 3) {
                int rb = 1 << (2 - wi);
#pragma unroll
                for (int h = 0; h < 2; ++h)
#pragma unroll
                    for (int r = 0; r < 8; ++r) {
                        if (r & rb) continue;
                        int r1 = r | rb;
                        float2 a0 = st[h][r], a1 = st[h][r1];
                        float2 n0, n1;
                        n0.x = g00.x * a0.x - g00.y * a0.y + g01.x * a1.x - g01.y * a1.y;
                        n0.y = g00.x * a0.y + g00.y * a0.x + g01.x * a1.y + g01.y * a1.x;
                        n1.x = g10.x * a0.x - g10.y * a0.y + g11.x * a1.x - g11.y * a1.y;
                        n1.y = g10.x * a0.y + g10.y * a0.x + g11.x * a1.y + g11.y * a1.x;
                        st[h][r] = n0; st[h][r1] = n1;
                    }
            } else {
                int mk = 1 << (7 - wi);
                bool hi = (ln & mk) != 0;
                float2 ga = hi ? g11 : g00;
                float2 gb = hi ? g10 : g01;
#pragma unroll
                for (int h = 0; h < 2; ++h)
#pragma unroll
                    for (int r = 0; r < 8; ++r) {
                        float2 m = st[h][r];
                        float2 p;
                        p.x = __shfl_xor_sync(0xffffffffu, m.x, mk);
                        p.y = __shfl_xor_sync(0xffffffffu, m.y, mk);
                        float2 n;
                        n.x = ga.x * m.x - ga.y * m.y + gb.x * p.x - gb.y * p.y;
                        n.y = ga.x * m.y + ga.y * m.x + gb.x * p.y + gb.y * p.x;
                        st[h][r] = n;
                    }
            }
        }
        // CNOT chain: new[j] = old[j ^ (j>>1)]
        int baseLane = (ln ^ (ln >> 1)) & 31;
        float2 tmp[2][8];
#pragma unroll
        for (int h = 0; h < 2; ++h)
#pragma unroll
            for (int r = 0; r < 8; ++r) {
                int sr = r ^ (r >> 1);
                int srcLane = baseLane ^ ((r & 1) << 4);
                tmp[h][r] = shfl2(st[h][sr], srcLane);
            }
#pragma unroll
        for (int h = 0; h < 2; ++h)
#pragma unroll
            for (int r = 0; r < 8; ++r) st[h][r] = tmp[h][r];
    }

#pragma unroll
    for (int h = 0; h < 2; ++h)
#pragma unroll
        for (int r = 0; r < 8; ++r) {
            int j = ln + 32 * r;
            Ms[SIDX(j, 2 * w + h)] = st[h][r];
        }
    __syncthreads();

    // -------- Phase B: BC slice (wire i, j in [32q, 32q+32)) --------
    int k = t >> 4, l = t & 15;
    int shift = 7 - i;
    float ar = 0.f, ai = 0.f;
#pragma unroll
    for (int jj = 0; jj < 32; ++jj) {
        int j = q * 32 + jj;
        float2 mk2 = Ms[SIDX(j, k)];
        float2 ml2 = Ms[SIDX(j, l)];
        float pr = mk2.x * ml2.x + mk2.y * ml2.y;
        float pi = mk2.x * ml2.y - mk2.y * ml2.x;
        float sg = ((j >> shift) & 1) ? -1.f : 1.f;
        ar = fmaf(sg, pr, ar);
        ai = fmaf(sg, pi, ai);
    }
    int d = (__popc(k) - __popc(l)) & 3;
    float val = (d == 0) ? ar : (d == 1) ? -ai : (d == 2) ? -ar : ai;
    int m = (((k >> 3) & 1) + ((l >> 3) & 1)) * 27 +
            (((k >> 2) & 1) + ((l >> 2) & 1)) * 9 +
            (((k >> 1) & 1) + ((l >> 1) & 1)) * 3 +
            ((k & 1) + (l & 1));
    atomicAdd(&Csh[m], val);
    __syncthreads();
    if (t < 81) g_Cpart[q][t * 8 + i] = Csh[t];

    // -------- Phase C: last block sums partials into g_C --------
    __threadfence();
    __syncthreads();
    if (t == 0) s_ticket = atomicAdd(&g_ticket, 1);
    __syncthreads();
    if (s_ticket == 63) {
        for (int idx = t; idx < 81 * 8; idx += 256) {
            float sum = 0.f;
#pragma unroll
            for (int qq = 0; qq < 8; ++qq) sum += __ldcg(&g_Cpart[qq][idx]);
            g_C[idx] = sum;
        }
        __threadfence();
        if (t == 0) g_ticket = 0;        // self-reset for graph replay
    }
}

// ---------------------------------------------------------------------------
// K2: TWO threads per sample (lane pair), 1024 blocks x 128 threads.
// Lane parity selects c-half {0..3} / {4..8} (padded to 5 with a zero-masked
// term -> uniform instruction stream). C duplicated in smem at a 96-byte bank
// offset so the two lane groups' LDS.128 hit disjoint banks. Combine via
// shfl_xor(1) + packed add; paired lanes write adjacent 16B chunks.
// ---------------------------------------------------------------------------
__global__ void __launch_bounds__(128) qmain(const float* __restrict__ x,
                                             float* __restrict__ out) {
    __shared__ __align__(16) float Csmem[376 + 360];   // CsA[360], gap, CsB[360]
    float* CsA = Csmem;
    float* CsB = Csmem + 376;                          // +1504 B; banks offset 24

    int t = threadIdx.x;
    for (int idx = t; idx < 360; idx += 128) {
        int i = idx & 7, r = idx >> 3;
        int a = r / 5, cc = r - a * 5;
        CsA[idx] = __ldcg(&g_C[(a * 9 + cc) * 8 + i]);
        CsB[idx] = __ldcg(&g_C[(a * 9 + 4 + cc) * 8 + i]);
    }
    __syncthreads();

    int s = blockIdx.x * 64 + (t >> 1);
    int half = t & 1;
    const float QP = 0.78539816339744831f;  // pi/4

    float4 xv = __ldg(reinterpret_cast<const float4*>(x) + s);
    float c0, s_0, c1, s_1, c2, s_2, c3, s_3;
    __sincosf((xv.x + 1.f) * QP, &s_0, &c0);
    __sincosf((xv.y + 1.f) * QP, &s_1, &c1);
    __sincosf((xv.z + 1.f) * QP, &s_2, &c2);
    __sincosf((xv.w + 1.f) * QP, &s_3, &c3);
    float u0[3] = {c0 * c0, c0 * s_0, s_0 * s_0};
    float u1[3] = {c1 * c1, c1 * s_1, s_1 * s_1};
    float u2[3] = {c2 * c2, c2 * s_2, s_2 * s_2};
    float u3[3] = {c3 * c3, c3 * s_3, s_3 * s_3};

    ull u01d[9];
#pragma unroll
    for (int a = 0; a < 3; ++a)
#pragma unroll
        for (int c = 0; c < 3; ++c)
            u01d[a * 3 + c] = dup2(u0[a] * u1[c]);

    float u23f[9];
#pragma unroll
    for (int a = 0; a < 3; ++a)
#pragma unroll
        for (int c = 0; c < 3; ++c)
            u23f[a * 3 + c] = u2[a] * u3[c];

    // my 5 c-slots: half0 -> c=0..3 + masked dummy; half1 -> c=4..8
    ull u23d[5];
#pragma unroll
    for (int cc = 0; cc < 5; ++cc) {
        float v = half ? u23f[4 + cc] : ((cc < 4) ? u23f[cc] : 0.f);
        u23d[cc] = dup2(v);
    }

    const float* Cbase = half ? CsB : CsA;

    ull acc0 = 0ull, acc1 = 0ull, acc2 = 0ull, acc3 = 0ull;
#pragma unroll
    for (int a = 0; a < 9; ++a) {
#pragma unroll
        for (int cc = 0; cc < 5; ++cc) {
            const ull* cp = reinterpret_cast<const ull*>(Cbase + (a * 5 + cc) * 8);
            ull pp = mul2(u01d[a], u23d[cc]);
            ffma2(acc0, cp[0], pp);
            ffma2(acc1, cp[1], pp);
            ffma2(acc2, cp[2], pp);
            ffma2(acc3, cp[3], pp);
        }
    }

    // combine the two halves of each sample
    acc0 = add2(acc0, __shfl_xor_sync(0xffffffffu, acc0, 1));
    acc1 = add2(acc1, __shfl_xor_sync(0xffffffffu, acc1, 1));
    acc2 = add2(acc2, __shfl_xor_sync(0xffffffffu, acc2, 1));
    acc3 = add2(acc3, __shfl_xor_sync(0xffffffffu, acc3, 1));

    float2 p0 = *reinterpret_cast<float2*>(&acc0);
    float2 p1 = *reinterpret_cast<float2*>(&acc1);
    float2 p2 = *reinterpret_cast<float2*>(&acc2);
    float2 p3 = *reinterpret_cast<float2*>(&acc3);
    float4 lo = make_float4(p0.x, p0.y, p1.x, p1.y);
    float4 hi = make_float4(p2.x, p2.y, p3.x, p3.y);
    float4* o = reinterpret_cast<float4*>(out + (size_t)s * 8);
    o[half] = half ? hi : lo;
}

// ---------------------------------------------------------------------------
extern "C" void kernel_launch(void* const* d_in, const int* in_sizes, int n_in,
                              void* d_out, int out_size) {
    const float* x = (const float*)d_in[0];        // (65536, 4)
    const float* params = (const float*)d_in[1];   // (2, 8, 3)
    float* out = (float*)d_out;                    // (65536, 8)

    fused_setup<<<64, 256>>>(params);
    qmain<<<BATCH / 64, 128>>>(x, out);
}

// round 11
// speedup vs baseline: 1.1916x; 1.1916x over previous
#include <cuda_runtime.h>

#define DIM 256
#define NCOL 16
#define BATCH 65536
typedef unsigned long long ull;

__device__ float g_Cpart[8][81 * 8];   // per-j-chunk partial C tensors
__device__ float g_C[81 * 8];          // summed C (filled by last setup block)
__device__ unsigned g_ticket;          // block-completion ticket (self-resetting)

__device__ __forceinline__ float2 cmul(float2 a, float2 b) {
    return make_float2(a.x * b.x - a.y * b.y, a.x * b.y + a.y * b.x);
}
__device__ __forceinline__ void ffma2(ull& d, ull a, ull b) {
    asm("fma.rn.f32x2 %0, %1, %2, %0;" : "+l"(d) : "l"(a), "l"(b));
}
__device__ __forceinline__ ull mul2(ull a, ull b) {
    ull r;
    asm("mul.rn.f32x2 %0, %1, %2;" : "=l"(r) : "l"(a), "l"(b));
    return r;
}
__device__ __forceinline__ ull dup2(float p) {
    ull r;
    asm("mov.b64 %0, {%1, %2};" : "=l"(r) : "f"(p), "f"(p));
    return r;
}
__device__ __forceinline__ float2 shfl2(float2 v, int src) {
    float2 r;
    r.x = __shfl_sync(0xffffffffu, v.x, src);
    r.y = __shfl_sync(0xffffffffu, v.y, src);
    return r;
}

// swizzled smem index for M: row j (128 B), column XOR'd by j&15 -> conflict-free
#define SIDX(j, c) (((j) << 4) | ((c) ^ ((j) & 15)))

// ---------------------------------------------------------------------------
// K1 (fused setup): 64 blocks = (8 wires i) x (8 j-chunks q), 256 threads.
// Phase A: all-register sim of the 16 relevant columns (8 warps x 2 cols).
// Phase B: swizzled smem M; BC slice for (i, q) -> g_Cpart.
// Phase C: LAST block sums the 8 partials into g_C (threadfence+ticket).
// ---------------------------------------------------------------------------
__global__ void __launch_bounds__(256) fused_setup(const float* __restrict__ params) {
    __shared__ float2 Ms[DIM * NCOL];    // 32 KB, swizzled
    __shared__ float2 G[16][4];
    __shared__ float Csh[81];
    __shared__ unsigned s_ticket;

    int t = threadIdx.x;
    int ln = t & 31;
    int w = t >> 5;                      // warp id = column pair
    int i = blockIdx.x & 7;              // output wire
    int q = blockIdx.x >> 3;             // j chunk

    if (t < 16) {
        int layer = t >> 3, wi = t & 7;
        const float* p = params + layer * 24 + wi * 3;
        float cx, sx, cy, sy, cz, sz;
        __sincosf(0.5f * p[0], &sx, &cx);
        __sincosf(0.5f * p[1], &sy, &cy);
        __sincosf(0.5f * p[2], &sz, &cz);
        float2 a00 = make_float2( cy * cx,  sy * sx);
        float2 a01 = make_float2(-sy * cx, -cy * sx);
        float2 a10 = make_float2( sy * cx, -cy * sx);
        float2 a11 = make_float2( cy * cx, -sy * sx);
        float2 e0 = make_float2(cz, -sz), e1 = make_float2(cz, sz);
        G[t][0] = cmul(e0, a00);
        G[t][1] = cmul(e0, a01);
        G[t][2] = cmul(e1, a10);
        G[t][3] = cmul(e1, a11);
    }
    if (t < 81) Csh[t] = 0.f;
    __syncthreads();

    // -------- Phase A: register sim (warp w owns columns 2w, 2w+1) --------
    float2 st[2][8];
#pragma unroll
    for (int h = 0; h < 2; ++h)
#pragma unroll
        for (int r = 0; r < 8; ++r)
            st[h][r] = make_float2((r == w && ln == (h << 4)) ? 1.f : 0.f, 0.f);

#pragma unroll
    for (int layer = 0; layer < 2; ++layer) {
#pragma unroll
        for (int wi = 0; wi < 8; ++wi) {
            int g = layer * 8 + wi;
            float2 g00 = G[g][0], g01 = G[g][1], g10 = G[g][2], g11 = G[g][3];
            if (wi < 3) {
                int rb = 1 << (2 - wi);
#pragma unroll
                for (int h = 0; h < 2; ++h)
#pragma unroll
                    for (int r = 0; r < 8; ++r) {
                        if (r & rb) continue;
                        int r1 = r | rb;
                        float2 a0 = st[h][r], a1 = st[h][r1];
                        float2 n0, n1;
                        n0.x = g00.x * a0.x - g00.y * a0.y + g01.x * a1.x - g01.y * a1.y;
                        n0.y = g00.x * a0.y + g00.y * a0.x + g01.x * a1.y + g01.y * a1.x;
                        n1.x = g10.x * a0.x - g10.y * a0.y + g11.x * a1.x - g11.y * a1.y;
                        n1.y = g10.x * a0.y + g10.y * a0.x + g11.x * a1.y + g11.y * a1.x;
                        st[h][r] = n0; st[h][r1] = n1;
                    }
            } else {
                int mk = 1 << (7 - wi);
                bool hi = (ln & mk) != 0;
                float2 ga = hi ? g11 : g00;
                float2 gb = hi ? g10 : g01;
#pragma unroll
                for (int h = 0; h < 2; ++h)
#pragma unroll
                    for (int r = 0; r < 8; ++r) {
                        float2 m = st[h][r];
                        float2 p;
                        p.x = __shfl_xor_sync(0xffffffffu, m.x, mk);
                        p.y = __shfl_xor_sync(0xffffffffu, m.y, mk);
                        float2 n;
                        n.x = ga.x * m.x - ga.y * m.y + gb.x * p.x - gb.y * p.y;
                        n.y = ga.x * m.y + ga.y * m.x + gb.x * p.y + gb.y * p.x;
                        st[h][r] = n;
                    }
            }
        }
        // CNOT chain: new[j] = old[j ^ (j>>1)]
        int baseLane = (ln ^ (ln >> 1)) & 31;
        float2 tmp[2][8];
#pragma unroll
        for (int h = 0; h < 2; ++h)
#pragma unroll
            for (int r = 0; r < 8; ++r) {
                int sr = r ^ (r >> 1);
                int srcLane = baseLane ^ ((r & 1) << 4);
                tmp[h][r] = shfl2(st[h][sr], srcLane);
            }
#pragma unroll
        for (int h = 0; h < 2; ++h)
#pragma unroll
            for (int r = 0; r < 8; ++r) st[h][r] = tmp[h][r];
    }

#pragma unroll
    for (int h = 0; h < 2; ++h)
#pragma unroll
        for (int r = 0; r < 8; ++r) {
            int j = ln + 32 * r;
            Ms[SIDX(j, 2 * w + h)] = st[h][r];
        }
    __syncthreads();

    // -------- Phase B: BC slice (wire i, j in [32q, 32q+32)) --------
    int k = t >> 4, l = t & 15;
    int shift = 7 - i;
    float ar = 0.f, ai = 0.f;
#pragma unroll
    for (int jj = 0; jj < 32; ++jj) {
        int j = q * 32 + jj;
        float2 mk2 = Ms[SIDX(j, k)];
        float2 ml2 = Ms[SIDX(j, l)];
        float pr = mk2.x * ml2.x + mk2.y * ml2.y;
        float pi = mk2.x * ml2.y - mk2.y * ml2.x;
        float sg = ((j >> shift) & 1) ? -1.f : 1.f;
        ar = fmaf(sg, pr, ar);
        ai = fmaf(sg, pi, ai);
    }
    int d = (__popc(k) - __popc(l)) & 3;
    float val = (d == 0) ? ar : (d == 1) ? -ai : (d == 2) ? -ar : ai;
    int m = (((k >> 3) & 1) + ((l >> 3) & 1)) * 27 +
            (((k >> 2) & 1) + ((l >> 2) & 1)) * 9 +
            (((k >> 1) & 1) + ((l >> 1) & 1)) * 3 +
            ((k & 1) + (l & 1));
    atomicAdd(&Csh[m], val);
    __syncthreads();
    if (t < 81) g_Cpart[q][t * 8 + i] = Csh[t];

    // -------- Phase C: last block sums partials into g_C --------
    __threadfence();
    __syncthreads();
    if (t == 0) s_ticket = atomicAdd(&g_ticket, 1);
    __syncthreads();
    if (s_ticket == 63) {
        for (int idx = t; idx < 81 * 8; idx += 256) {
            float sum = 0.f;
#pragma unroll
            for (int qq = 0; qq < 8; ++qq) sum += __ldcg(&g_Cpart[qq][idx]);
            g_C[idx] = sum;
        }
        __threadfence();
        if (t == 0) g_ticket = 0;        // self-reset for graph replay
    }
}

// ---------------------------------------------------------------------------
// K2: lane pair shares one sample; even lane -> outputs 0-3, odd -> 4-7.
// Inner loop per (a,c): 1 LDS.128 + 1 mul2 + 2 ffma2 (4 inst). Half-offset
// folded into the C base pointer ONCE (no per-iter ALU, no padding, no
// divergent stream). 4096 warps for latency hiding. Each lane stores its own
// float4 (adjacent 16B -> coalesced); no shuffle combine.
// ---------------------------------------------------------------------------
__global__ void __launch_bounds__(256) qmain(const float* __restrict__ x,
                                             float* __restrict__ out) {
    __shared__ __align__(16) float Cs[81 * 8];
    int t = threadIdx.x;
    for (int idx = t; idx < 81 * 8; idx += 256)
        Cs[idx] = __ldcg(&g_C[idx]);
    __syncthreads();

    int gt = blockIdx.x * 256 + t;
    int s = gt >> 1;                     // sample
    int half = gt & 1;                   // output half
    const float QP = 0.78539816339744831f;  // pi/4

    float4 xv = __ldg(reinterpret_cast<const float4*>(x) + s);
    float c0, s_0, c1, s_1, c2, s_2, c3, s_3;
    __sincosf((xv.x + 1.f) * QP, &s_0, &c0);
    __sincosf((xv.y + 1.f) * QP, &s_1, &c1);
    __sincosf((xv.z + 1.f) * QP, &s_2, &c2);
    __sincosf((xv.w + 1.f) * QP, &s_3, &c3);
    float u0[3] = {c0 * c0, c0 * s_0, s_0 * s_0};
    float u1[3] = {c1 * c1, c1 * s_1, s_1 * s_1};
    float u2[3] = {c2 * c2, c2 * s_2, s_2 * s_2};
    float u3[3] = {c3 * c3, c3 * s_3, s_3 * s_3};

    ull u01d[9], u23d[9];
#pragma unroll
    for (int a = 0; a < 3; ++a)
#pragma unroll
        for (int c = 0; c < 3; ++c) {
            u01d[a * 3 + c] = dup2(u0[a] * u1[c]);
            u23d[a * 3 + c] = dup2(u2[a] * u3[c]);
        }

    // fold the half-offset into the base pointer once
    const float* Cb = Cs + half * 4;

    ull acc0 = 0ull, acc1 = 0ull;
#pragma unroll
    for (int a = 0; a < 9; ++a) {
#pragma unroll
        for (int c = 0; c < 9; ++c) {
            const ull* cp = reinterpret_cast<const ull*>(Cb + (a * 9 + c) * 8);
            ull pp = mul2(u01d[a], u23d[c]);
            ffma2(acc0, cp[0], pp);
            ffma2(acc1, cp[1], pp);
        }
    }

    float2 p0 = *reinterpret_cast<float2*>(&acc0);
    float2 p1 = *reinterpret_cast<float2*>(&acc1);
    reinterpret_cast<float4*>(out + (size_t)s * 8)[half] =
        make_float4(p0.x, p0.y, p1.x, p1.y);
}

// ---------------------------------------------------------------------------
extern "C" void kernel_launch(void* const* d_in, const int* in_sizes, int n_in,
                              void* d_out, int out_size) {
    const float* x = (const float*)d_in[0];        // (65536, 4)
    const float* params = (const float*)d_in[1];   // (2, 8, 3)
    float* out = (float*)d_out;                    // (65536, 8)

    fused_setup<<<64, 256>>>(params);
    qmain<<<BATCH * 2 / 256, 256>>>(x, out);
}

// round 13
// speedup vs baseline: 1.2288x; 1.0312x over previous
#include <cuda_runtime.h>

#define DIM 256
#define NCOL 16
#define BATCH 65536
typedef unsigned long long ull;

__device__ float g_Cpart[8][81 * 8];   // per-j-chunk partial C tensors
__device__ float g_C[81 * 8];          // summed C (filled by last setup block)
__device__ unsigned g_ticket;          // block-completion ticket (self-resetting)

__device__ __forceinline__ float2 cmul(float2 a, float2 b) {
    return make_float2(a.x * b.x - a.y * b.y, a.x * b.y + a.y * b.x);
}
__device__ __forceinline__ void ffma2(ull& d, ull a, ull b) {
    asm("fma.rn.f32x2 %0, %1, %2, %0;" : "+l"(d) : "l"(a), "l"(b));
}
__device__ __forceinline__ ull mul2(ull a, ull b) {
    ull r;
    asm("mul.rn.f32x2 %0, %1, %2;" : "=l"(r) : "l"(a), "l"(b));
    return r;
}
__device__ __forceinline__ ull dup2(float p) {
    ull r;
    asm("mov.b64 %0, {%1, %2};" : "=l"(r) : "f"(p), "f"(p));
    return r;
}
__device__ __forceinline__ float2 shfl2(float2 v, int src) {
    float2 r;
    r.x = __shfl_sync(0xffffffffu, v.x, src);
    r.y = __shfl_sync(0xffffffffu, v.y, src);
    return r;
}

// swizzled smem index for M: row j (128 B), column XOR'd by j&15 -> conflict-free
#define SIDX(j, c) (((j) << 4) | ((c) ^ ((j) & 15)))

// ---------------------------------------------------------------------------
// K1 (fused setup): 64 blocks = (8 wires i) x (8 j-chunks q), 256 threads.
// Phase A: all-register sim of the 16 relevant columns (8 warps x 2 cols).
// Phase B: swizzled smem M; BC slice for (i, q) -> g_Cpart.
// Phase C: LAST block sums the 8 partials into g_C (threadfence+ticket).
// ---------------------------------------------------------------------------
__global__ void __launch_bounds__(256) fused_setup(const float* __restrict__ params) {
    __shared__ float2 Ms[DIM * NCOL];    // 32 KB, swizzled
    __shared__ float2 G[16][4];
    __shared__ float Csh[81];
    __shared__ unsigned s_ticket;

    int t = threadIdx.x;
    int ln = t & 31;
    int w = t >> 5;                      // warp id = column pair
    int i = blockIdx.x & 7;              // output wire
    int q = blockIdx.x >> 3;             // j chunk

    if (t < 16) {
        int layer = t >> 3, wi = t & 7;
        const float* p = params + layer * 24 + wi * 3;
        float cx, sx, cy, sy, cz, sz;
        __sincosf(0.5f * p[0], &sx, &cx);
        __sincosf(0.5f * p[1], &sy, &cy);
        __sincosf(0.5f * p[2], &sz, &cz);
        float2 a00 = make_float2( cy * cx,  sy * sx);
        float2 a01 = make_float2(-sy * cx, -cy * sx);
        float2 a10 = make_float2( sy * cx, -cy * sx);
        float2 a11 = make_float2( cy * cx, -sy * sx);
        float2 e0 = make_float2(cz, -sz), e1 = make_float2(cz, sz);
        G[t][0] = cmul(e0, a00);
        G[t][1] = cmul(e0, a01);
        G[t][2] = cmul(e1, a10);
        G[t][3] = cmul(e1, a11);
    }
    if (t < 81) Csh[t] = 0.f;
    __syncthreads();

    // -------- Phase A: register sim (warp w owns columns 2w, 2w+1) --------
    float2 st[2][8];
#pragma unroll
    for (int h = 0; h < 2; ++h)
#pragma unroll
        for (int r = 0; r < 8; ++r)
            st[h][r] = make_float2((r == w && ln == (h << 4)) ? 1.f : 0.f, 0.f);

#pragma unroll
    for (int layer = 0; layer < 2; ++layer) {
#pragma unroll
        for (int wi = 0; wi < 8; ++wi) {
            int g = layer * 8 + wi;
            float2 g00 = G[g][0], g01 = G[g][1], g10 = G[g][2], g11 = G[g][3];
            if (wi < 3) {
                int rb = 1 << (2 - wi);
#pragma unroll
                for (int h = 0; h < 2; ++h)
#pragma unroll
                    for (int r = 0; r < 8; ++r) {
                        if (r & rb) continue;
                        int r1 = r | rb;
                        float2 a0 = st[h][r], a1 = st[h][r1];
                        float2 n0, n1;
                        n0.x = g00.x * a0.x - g00.y * a0.y + g01.x * a1.x - g01.y * a1.y;
                        n0.y = g00.x * a0.y + g00.y * a0.x + g01.x * a1.y + g01.y * a1.x;
                        n1.x = g10.x * a0.x - g10.y * a0.y + g11.x * a1.x - g11.y * a1.y;
                        n1.y = g10.x * a0.y + g10.y * a0.x + g11.x * a1.y + g11.y * a1.x;
                        st[h][r] = n0; st[h][r1] = n1;
                    }
            } else {
                int mk = 1 << (7 - wi);
                bool hi = (ln & mk) != 0;
                float2 ga = hi ? g11 : g00;
                float2 gb = hi ? g10 : g01;
#pragma unroll
                for (int h = 0; h < 2; ++h)
#pragma unroll
                    for (int r = 0; r < 8; ++r) {
                        float2 m = st[h][r];
                        float2 p;
                        p.x = __shfl_xor_sync(0xffffffffu, m.x, mk);
                        p.y = __shfl_xor_sync(0xffffffffu, m.y, mk);
                        float2 n;
                        n.x = ga.x * m.x - ga.y * m.y + gb.x * p.x - gb.y * p.y;
                        n.y = ga.x * m.y + ga.y * m.x + gb.x * p.y + gb.y * p.x;
                        st[h][r] = n;
                    }
            }
        }
        // CNOT chain: new[j] = old[j ^ (j>>1)]
        int baseLane = (ln ^ (ln >> 1)) & 31;
        float2 tmp[2][8];
#pragma unroll
        for (int h = 0; h < 2; ++h)
#pragma unroll
            for (int r = 0; r < 8; ++r) {
                int sr = r ^ (r >> 1);
                int srcLane = baseLane ^ ((r & 1) << 4);
                tmp[h][r] = shfl2(st[h][sr], srcLane);
            }
#pragma unroll
        for (int h = 0; h < 2; ++h)
#pragma unroll
            for (int r = 0; r < 8; ++r) st[h][r] = tmp[h][r];
    }

#pragma unroll
    for (int h = 0; h < 2; ++h)
#pragma unroll
        for (int r = 0; r < 8; ++r) {
            int j = ln + 32 * r;
            Ms[SIDX(j, 2 * w + h)] = st[h][r];
        }
    __syncthreads();

    // -------- Phase B: BC slice (wire i, j in [32q, 32q+32)) --------
    int k = t >> 4, l = t & 15;
    int shift = 7 - i;
    float ar = 0.f, ai = 0.f;
#pragma unroll
    for (int jj = 0; jj < 32; ++jj) {
        int j = q * 32 + jj;
        float2 mk2 = Ms[SIDX(j, k)];
        float2 ml2 = Ms[SIDX(j, l)];
        float pr = mk2.x * ml2.x + mk2.y * ml2.y;
        float pi = mk2.x * ml2.y - mk2.y * ml2.x;
        float sg = ((j >> shift) & 1) ? -1.f : 1.f;
        ar = fmaf(sg, pr, ar);
        ai = fmaf(sg, pi, ai);
    }
    int d = (__popc(k) - __popc(l)) & 3;
    float val = (d == 0) ? ar : (d == 1) ? -ai : (d == 2) ? -ar : ai;
    int m = (((k >> 3) & 1) + ((l >> 3) & 1)) * 27 +
            (((k >> 2) & 1) + ((l >> 2) & 1)) * 9 +
            (((k >> 1) & 1) + ((l >> 1) & 1)) * 3 +
            ((k & 1) + (l & 1));
    atomicAdd(&Csh[m], val);
    __syncthreads();
    if (t < 81) g_Cpart[q][t * 8 + i] = Csh[t];

    // -------- Phase C: last block sums partials into g_C --------
    __threadfence();
    __syncthreads();
    if (t == 0) s_ticket = atomicAdd(&g_ticket, 1);
    __syncthreads();
    if (s_ticket == 63) {
        for (int idx = t; idx < 81 * 8; idx += 256) {
            float sum = 0.f;
#pragma unroll
            for (int qq = 0; qq < 8; ++qq) sum += __ldcg(&g_Cpart[qq][idx]);
            g_C[idx] = sum;
        }
        __threadfence();
        if (t == 0) g_ticket = 0;        // self-reset for graph replay
    }
}

// ---------------------------------------------------------------------------
// K2: lane pair shares one sample (even lane -> outputs 0-3, odd -> 4-7).
// Software-pipelined: per a-row, stage all 9 C pairs via 9 independent
// LDS.128 (MLP=9), THEN run 27 fma-pipe instructions. One LDS-latency
// exposure per 36 instructions instead of one per 4.
// NOTE: each (a,c) coefficient block is 32 B, so the ulonglong2 index is
// 2*(a*9+c) — the R12 bug was using (a*9+c) (16 B stride).
// ---------------------------------------------------------------------------
__global__ void __launch_bounds__(256) qmain(const float* __restrict__ x,
                                             float* __restrict__ out) {
    __shared__ __align__(16) float Cs[81 * 8];
    int t = threadIdx.x;
    for (int idx = t; idx < 81 * 8; idx += 256)
        Cs[idx] = __ldcg(&g_C[idx]);

    int gt = blockIdx.x * 256 + t;
    int s = gt >> 1;                     // sample
    int half = gt & 1;                   // output half
    const float QP = 0.78539816339744831f;  // pi/4

    float4 xv = __ldg(reinterpret_cast<const float4*>(x) + s);
    float c0, s_0, c1, s_1, c2, s_2, c3, s_3;
    __sincosf((xv.x + 1.f) * QP, &s_0, &c0);
    __sincosf((xv.y + 1.f) * QP, &s_1, &c1);
    __sincosf((xv.z + 1.f) * QP, &s_2, &c2);
    __sincosf((xv.w + 1.f) * QP, &s_3, &c3);
    float u0[3] = {c0 * c0, c0 * s_0, s_0 * s_0};
    float u1[3] = {c1 * c1, c1 * s_1, s_1 * s_1};
    float u2[3] = {c2 * c2, c2 * s_2, s_2 * s_2};
    float u3[3] = {c3 * c3, c3 * s_3, s_3 * s_3};

    ull u01d[9], u23d[9];
#pragma unroll
    for (int a = 0; a < 3; ++a)
#pragma unroll
        for (int c = 0; c < 3; ++c) {
            u01d[a * 3 + c] = dup2(u0[a] * u1[c]);
            u23d[a * 3 + c] = dup2(u2[a] * u3[c]);
        }

    __syncthreads();

    // fold the half-offset into the base pointer once (16B-aligned)
    const ulonglong2* Cb =
        reinterpret_cast<const ulonglong2*>(Cs + half * 4);

    ull acc0 = 0ull, acc1 = 0ull;
#pragma unroll
    for (int a = 0; a < 9; ++a) {
        // stage the whole a-row: 9 independent LDS.128 (32-B element stride)
        ulonglong2 cr[9];
#pragma unroll
        for (int c = 0; c < 9; ++c) cr[c] = Cb[2 * (a * 9 + c)];
        // 27 fma-pipe instructions, no loads
#pragma unroll
        for (int c = 0; c < 9; ++c) {
            ull pp = mul2(u01d[a], u23d[c]);
            ffma2(acc0, cr[c].x, pp);
            ffma2(acc1, cr[c].y, pp);
        }
    }

    float2 p0 = *reinterpret_cast<float2*>(&acc0);
    float2 p1 = *reinterpret_cast<float2*>(&acc1);
    reinterpret_cast<float4*>(out + (size_t)s * 8)[half] =
        make_float4(p0.x, p0.y, p1.x, p1.y);
}

// ---------------------------------------------------------------------------
extern "C" void kernel_launch(void* const* d_in, const int* in_sizes, int n_in,
                              void* d_out, int out_size) {
    const float* x = (const float*)d_in[0];        // (65536, 4)
    const float* params = (const float*)d_in[1];   // (2, 8, 3)
    float* out = (float*)d_out;                    // (65536, 8)

    fused_setup<<<64, 256>>>(params);
    qmain<<<BATCH * 2 / 256, 256>>>(x, out);
}